// round 7
// baseline (speedup 1.0000x reference)
#include <cuda_runtime.h>
#include <math.h>

#define NN    50000
#define EE    8192
#define INDIM 256
#define HIDD  256
#define TDIM  32
#define MSGD  288   // INDIM + TDIM
#define G3H   768
#define EMBD  512

// ---------------- scratch (static device globals; no runtime allocation) ----
static __device__ __align__(128) float g_msg [EE * MSGD];
static __device__ __align__(128) float g_gi  [EE * G3H];
static __device__ __align__(128) float g_WhhT[HIDD * G3H];
static __device__ __align__(128) float g_mem [NN * HIDD];
static __device__ __align__(128) float g_emb [NN * EMBD];
static __device__ __align__(128) float g_buf0[NN * HIDD];
static __device__ __align__(128) float g_buf1[NN * HIDD];
static __device__ __align__(128) float g_qe  [EE * 512];
static __device__ __align__(128) float g_ke  [EE * 512];
static __device__ __align__(128) float g_ve  [EE * 512];
static __device__ float g_alpha[EE * 2];
static __device__ float g_ex   [EE * 2];
static __device__ float g_m    [NN * 2];
static __device__ float g_denom[NN * 2];
static __device__ int   g_chain_edge[EE];
static __device__ int   g_chain_dst [EE];
static __device__ int   g_is_head   [EE];

// ---------------- sort: single-block bitonic on 64-bit keys -----------------
// key = (dst << 45) | (time_bits << 13) | idx
// time in [0,1) -> float bits < 2^30, idx < 2^13, dst < 2^16: no overlap.
// Per-dst order = (time, original index) == JAX stable argsort restricted to dst.
__global__ void sort_kernel(const float* __restrict__ et, const int* __restrict__ ei) {
    extern __shared__ unsigned long long key[];
    const int n = EE;
    for (int i = threadIdx.x; i < n; i += blockDim.x) {
        unsigned long long tb = (unsigned long long)__float_as_uint(et[i]);
        unsigned long long d  = (unsigned long long)(unsigned)ei[EE + i];
        key[i] = (d << 45) | (tb << 13) | (unsigned long long)i;
    }
    __syncthreads();
    for (int k = 2; k <= n; k <<= 1) {
        for (int j = k >> 1; j > 0; j >>= 1) {
            for (int t = threadIdx.x; t < n; t += blockDim.x) {
                int ixj = t ^ j;
                if (ixj > t) {
                    unsigned long long a = key[t], b = key[ixj];
                    bool up = ((t & k) == 0);
                    if ((a > b) == up) { key[t] = b; key[ixj] = a; }
                }
            }
            __syncthreads();
        }
    }
    for (int i = threadIdx.x; i < n; i += blockDim.x) {
        unsigned long long kv = key[i];
        g_chain_edge[i] = (int)(kv & 0x1FFFULL);
        g_chain_dst[i]  = (int)(kv >> 45);
    }
    __syncthreads();
    for (int i = threadIdx.x; i < n; i += blockDim.x)
        g_is_head[i] = (i == 0) || (g_chain_dst[i] != g_chain_dst[i - 1]);
}

// ---------------- small helpers ---------------------------------------------
__global__ void msg_kernel(const float* __restrict__ x, const int* __restrict__ src,
                           const float* __restrict__ et, const float* __restrict__ tW,
                           const float* __restrict__ tb) {
    int e = blockIdx.x, c = threadIdx.x;
    float v;
    if (c < INDIM) v = x[(size_t)src[e] * INDIM + c];
    else { int cc = c - INDIM; v = fmaxf(fmaf(et[e], tW[cc], tb[cc]), 0.0f); }
    g_msg[(size_t)e * MSGD + c] = v;
}

__global__ void transpose_whh(const float* __restrict__ Whh) {
    int idx = blockIdx.x * 256 + threadIdx.x;
    if (idx < G3H * HIDD) {
        int j = idx / HIDD, i = idx % HIDD;
        g_WhhT[i * G3H + j] = Whh[idx];
    }
}

__global__ void copy_mem_kernel(const float* __restrict__ memin) {
    int idx = blockIdx.x * 256 + threadIdx.x;
    if (idx < NN * HIDD) g_mem[idx] = memin[idx];
}

__global__ void concat_kernel() {
    int idx = blockIdx.x * 256 + threadIdx.x;
    if (idx < NN * HIDD) {
        int n = idx / HIDD, c = idx % HIDD;
        g_emb[(size_t)n * EMBD + HIDD + c] = g_mem[idx];
    }
}

__global__ void init_md_kernel() {
    int idx = blockIdx.x * 256 + threadIdx.x;
    if (idx < NN * 2) {
        g_m[idx] = __int_as_float(0xff800000);  // -inf
        g_denom[idx] = 0.0f;
    }
}

__global__ void relu_kernel(float* __restrict__ buf, int n) {
    int idx = blockIdx.x * 256 + threadIdx.x;
    if (idx < n) buf[idx] = fmaxf(buf[idx], 0.0f);
}

// ---------------- GRU chains ------------------------------------------------
// One 256-thread block per chain head. Chain = consecutive sorted entries with
// the same dst, in (time, idx) order. Matvec with Whh^T skipped while h == 0
// (gh reduces to bhh), which removes ~92% of the matvecs for this workload
// while staying correct for arbitrary initial memory.
__global__ void __launch_bounds__(HIDD) gru_chain_kernel(const float* __restrict__ bhh) {
    int i0 = blockIdx.x;
    if (!g_is_head[i0]) return;
    int t = threadIdx.x;
    int d = g_chain_dst[i0];
    __shared__ float sh[HIDD];
    float h = g_mem[d * HIDD + t];
    sh[t] = h;
    int nz = __syncthreads_or(h != 0.0f);
    float b0 = bhh[t], b1 = bhh[HIDD + t], b2 = bhh[2 * HIDD + t];
    for (int i = i0; i < EE && g_chain_dst[i] == d; ++i) {
        int e = g_chain_edge[i];
        float gh0 = b0, gh1 = b1, gh2 = b2;
        if (nz) {
            #pragma unroll 4
            for (int kk = 0; kk < HIDD; ++kk) {
                float v = sh[kk];
                const float* wp = &g_WhhT[kk * G3H + t];
                gh0 += v * wp[0];
                gh1 += v * wp[HIDD];
                gh2 += v * wp[2 * HIDD];
            }
        }
        const float* gi = &g_gi[(size_t)e * G3H];
        float r  = 1.0f / (1.0f + expf(-(gi[t] + gh0)));
        float z  = 1.0f / (1.0f + expf(-(gi[HIDD + t] + gh1)));
        float nv = tanhf(gi[2 * HIDD + t] + r * gh2);
        float hn = (1.0f - z) * nv + z * h;
        __syncthreads();
        sh[t] = hn;
        h = hn;
        nz = __syncthreads_or(hn != 0.0f);
    }
    g_mem[d * HIDD + t] = h;
}

// ---------------- generic fp32 GEMM: C = act(gather(A) @ W^T + bias) --------
// W row-major [Ncols][K]. 64x64 block tile, 256 threads, 4x4 microtile,
// float4 smem loads (2x LDS.128 per 16 FFMA). K % 16 == 0, Ncols % 64 == 0.
#define BM 64
#define BN 64
#define BK 16
__global__ void __launch_bounds__(256) gemm_kernel(
    const float* __restrict__ A, int lda, const int* __restrict__ gather, int M,
    const float* __restrict__ W, int K, const float* __restrict__ bias,
    float* __restrict__ C, int ldc, int act)
{
    __shared__ float As[BK][BM + 4];
    __shared__ float Ws[BK][BN + 4];
    int tid = threadIdx.x;
    int tx = tid & 15, ty = tid >> 4;
    int lr = tid >> 2;
    int lk = (tid & 3) * 4;
    int arow = blockIdx.y * BM + lr;
    if (arow >= M) arow = M - 1;
    int ga = gather ? gather[arow] : arow;
    const float* Ab = A + (size_t)ga * lda;
    const float* Wb = W + (size_t)(blockIdx.x * BN + lr) * K;
    float acc[4][4];
    #pragma unroll
    for (int i = 0; i < 4; i++)
        #pragma unroll
        for (int j = 0; j < 4; j++) acc[i][j] = 0.0f;

    for (int k0 = 0; k0 < K; k0 += BK) {
        float4 av = *(const float4*)(Ab + k0 + lk);
        float4 wv = *(const float4*)(Wb + k0 + lk);
        As[lk + 0][lr] = av.x; As[lk + 1][lr] = av.y;
        As[lk + 2][lr] = av.z; As[lk + 3][lr] = av.w;
        Ws[lk + 0][lr] = wv.x; Ws[lk + 1][lr] = wv.y;
        Ws[lk + 2][lr] = wv.z; Ws[lk + 3][lr] = wv.w;
        __syncthreads();
        #pragma unroll
        for (int kk = 0; kk < BK; kk++) {
            float4 a = *(const float4*)&As[kk][ty * 4];
            float4 b = *(const float4*)&Ws[kk][tx * 4];
            acc[0][0] += a.x * b.x; acc[0][1] += a.x * b.y; acc[0][2] += a.x * b.z; acc[0][3] += a.x * b.w;
            acc[1][0] += a.y * b.x; acc[1][1] += a.y * b.y; acc[1][2] += a.y * b.z; acc[1][3] += a.y * b.w;
            acc[2][0] += a.z * b.x; acc[2][1] += a.z * b.y; acc[2][2] += a.z * b.z; acc[2][3] += a.z * b.w;
            acc[3][0] += a.w * b.x; acc[3][1] += a.w * b.y; acc[3][2] += a.w * b.z; acc[3][3] += a.w * b.w;
        }
        __syncthreads();
    }
    int cbase = blockIdx.x * BN + tx * 4;
    float bs0 = bias[cbase], bs1 = bias[cbase + 1], bs2 = bias[cbase + 2], bs3 = bias[cbase + 3];
    #pragma unroll
    for (int i = 0; i < 4; i++) {
        int r = blockIdx.y * BM + ty * 4 + i;
        if (r < M) {
            float* Cp = C + (size_t)r * ldc + cbase;
            float v0 = acc[i][0] + bs0, v1 = acc[i][1] + bs1;
            float v2 = acc[i][2] + bs2, v3 = acc[i][3] + bs3;
            if (act) { v0 = fmaxf(v0, 0.f); v1 = fmaxf(v1, 0.f); v2 = fmaxf(v2, 0.f); v3 = fmaxf(v3, 0.f); }
            Cp[0] = v0; Cp[1] = v1; Cp[2] = v2; Cp[3] = v3;
        }
    }
}

// ---------------- attention pieces ------------------------------------------
__device__ __forceinline__ void atomicMaxF(float* addr, float val) {
    int old = __float_as_int(*addr);
    while (__int_as_float(old) < val) {
        int assumed = old;
        old = atomicCAS((int*)addr, assumed, __float_as_int(val));
        if (old == assumed) break;
    }
}

__global__ void alpha_kernel(const float* __restrict__ qe, const float* __restrict__ ke,
                             const int* __restrict__ dst) {
    int e = blockIdx.x * 8 + (threadIdx.x >> 5);
    int lane = threadIdx.x & 31;
    const float* q = qe + (size_t)e * 512;
    const float* k = ke + (size_t)e * 512;
    float s0 = 0.f, s1 = 0.f;
    #pragma unroll
    for (int c = lane; c < 256; c += 32) {
        s0 = fmaf(q[c], k[c], s0);
        s1 = fmaf(q[256 + c], k[256 + c], s1);
    }
    #pragma unroll
    for (int o = 16; o > 0; o >>= 1) {
        s0 += __shfl_xor_sync(0xffffffffu, s0, o);
        s1 += __shfl_xor_sync(0xffffffffu, s1, o);
    }
    if (lane == 0) {
        const float scale = 0.0625f;  // 1/sqrt(256)
        float a0 = s0 * scale, a1 = s1 * scale;
        int d = dst[e];
        g_alpha[e * 2] = a0; g_alpha[e * 2 + 1] = a1;
        atomicMaxF(&g_m[d * 2], a0);
        atomicMaxF(&g_m[d * 2 + 1], a1);
    }
}

__global__ void ex_kernel(const int* __restrict__ dst) {
    int idx = blockIdx.x * 256 + threadIdx.x;
    if (idx < EE * 2) {
        int e = idx >> 1, h = idx & 1;
        int d = dst[e];
        float v = expf(g_alpha[idx] - g_m[d * 2 + h]);
        g_ex[idx] = v;
        atomicAdd(&g_denom[d * 2 + h], v);
    }
}

__global__ void scatter_kernel(const float* __restrict__ ve, const int* __restrict__ dst,
                               float* __restrict__ C) {
    int e = blockIdx.x, c = threadIdx.x;
    int d = dst[e];
    float w0 = g_ex[e * 2]     / g_denom[d * 2]     * 0.5f;
    float w1 = g_ex[e * 2 + 1] / g_denom[d * 2 + 1] * 0.5f;
    atomicAdd(&C[(size_t)d * HIDD + c],
              w0 * ve[(size_t)e * 512 + c] + w1 * ve[(size_t)e * 512 + 256 + c]);
}

// ---------------- launch ----------------------------------------------------
static void run_conv_layer(const float* xin, int lda, int K,
                           const float* qW, const float* qb,
                           const float* kW, const float* kb,
                           const float* vW, const float* vb,
                           const float* sW, const float* sb,
                           const int* src, const int* dst,
                           float* p_qe, float* p_ke, float* p_ve, float* outbuf)
{
    dim3 ge(512 / BN, EE / BM);
    gemm_kernel<<<ge, 256>>>(xin, lda, dst, EE, qW, K, qb, p_qe, 512, 0);
    gemm_kernel<<<ge, 256>>>(xin, lda, src, EE, kW, K, kb, p_ke, 512, 0);
    gemm_kernel<<<ge, 256>>>(xin, lda, src, EE, vW, K, vb, p_ve, 512, 0);
    dim3 gs(HIDD / BN, (NN + BM - 1) / BM);
    gemm_kernel<<<gs, 256>>>(xin, lda, nullptr, NN, sW, K, sb, outbuf, HIDD, 0);
    init_md_kernel<<<(NN * 2 + 255) / 256, 256>>>();
    alpha_kernel<<<EE / 8, 256>>>(p_qe, p_ke, dst);
    ex_kernel<<<(EE * 2 + 255) / 256, 256>>>(dst);
    scatter_kernel<<<EE, HIDD>>>(p_ve, dst, outbuf);
    relu_kernel<<<(NN * HIDD + 255) / 256, 256>>>(outbuf, NN * HIDD);
}

extern "C" void kernel_launch(void* const* d_in, const int* in_sizes, int n_in,
                              void* d_out, int out_size) {
    (void)in_sizes; (void)n_in; (void)out_size;
    const float* x      = (const float*)d_in[0];
    const int*   ei     = (const int*)  d_in[1];
    const float* et     = (const float*)d_in[2];
    const float* memin  = (const float*)d_in[3];
    const float* Wih    = (const float*)d_in[4];
    const float* Whh    = (const float*)d_in[5];
    const float* bih    = (const float*)d_in[6];
    const float* bhh    = (const float*)d_in[7];
    const float* timeW  = (const float*)d_in[8];
    const float* timeB  = (const float*)d_in[9];
    const float* featW  = (const float*)d_in[10];
    const float* featB  = (const float*)d_in[11];
    const float* c0_qW = (const float*)d_in[12]; const float* c0_qb = (const float*)d_in[13];
    const float* c0_kW = (const float*)d_in[14]; const float* c0_kb = (const float*)d_in[15];
    const float* c0_vW = (const float*)d_in[16]; const float* c0_vb = (const float*)d_in[17];
    const float* c0_sW = (const float*)d_in[18]; const float* c0_sb = (const float*)d_in[19];
    const float* c1_qW = (const float*)d_in[20]; const float* c1_qb = (const float*)d_in[21];
    const float* c1_kW = (const float*)d_in[22]; const float* c1_kb = (const float*)d_in[23];
    const float* c1_vW = (const float*)d_in[24]; const float* c1_vb = (const float*)d_in[25];
    const float* c1_sW = (const float*)d_in[26]; const float* c1_sb = (const float*)d_in[27];
    const float* clsW  = (const float*)d_in[28]; const float* clsB  = (const float*)d_in[29];
    float* out = (float*)d_out;

    const int* src = ei;
    const int* dst = ei + EE;

    float *p_msg, *p_gi, *p_mem, *p_emb, *p_buf0, *p_buf1, *p_qe, *p_ke, *p_ve;
    cudaGetSymbolAddress((void**)&p_msg,  g_msg);
    cudaGetSymbolAddress((void**)&p_gi,   g_gi);
    cudaGetSymbolAddress((void**)&p_mem,  g_mem);
    cudaGetSymbolAddress((void**)&p_emb,  g_emb);
    cudaGetSymbolAddress((void**)&p_buf0, g_buf0);
    cudaGetSymbolAddress((void**)&p_buf1, g_buf1);
    cudaGetSymbolAddress((void**)&p_qe,   g_qe);
    cudaGetSymbolAddress((void**)&p_ke,   g_ke);
    cudaGetSymbolAddress((void**)&p_ve,   g_ve);

    cudaFuncSetAttribute(sort_kernel, cudaFuncAttributeMaxDynamicSharedMemorySize, 65536);

    // 1) sort edges into per-dst time-ordered chains
    sort_kernel<<<1, 1024, 65536>>>(et, ei);

    // 2) gi = [x[src] | relu(time)] @ Wih^T + bih  (batched input half of GRU)
    msg_kernel<<<EE, MSGD>>>(x, src, et, timeW, timeB);
    gemm_kernel<<<dim3(G3H / BN, EE / BM), 256>>>(p_msg, MSGD, nullptr, EE,
                                                  Wih, MSGD, bih, p_gi, G3H, 0);

    // 3) GRU memory update (chains parallel over dst)
    transpose_whh<<<(G3H * HIDD + 255) / 256, 256>>>(Whh);
    copy_mem_kernel<<<(NN * HIDD + 255) / 256, 256>>>(memin);
    gru_chain_kernel<<<EE, HIDD>>>(bhh);

    // 4) emb = [relu(x @ featW^T + featB) | mem]
    gemm_kernel<<<dim3(INDIM / BN, (NN + BM - 1) / BM), 256>>>(
        x, INDIM, nullptr, NN, featW, INDIM, featB, p_emb, EMBD, 1);
    concat_kernel<<<(NN * HIDD + 255) / 256, 256>>>();

    // 5) two TransformerConv layers (Q/K/V per edge, skip for all nodes)
    run_conv_layer(p_emb, EMBD, EMBD, c0_qW, c0_qb, c0_kW, c0_kb, c0_vW, c0_vb,
                   c0_sW, c0_sb, src, dst, p_qe, p_ke, p_ve, p_buf0);
    run_conv_layer(p_buf0, HIDD, HIDD, c1_qW, c1_qb, c1_kW, c1_kb, c1_vW, c1_vb,
                   c1_sW, c1_sb, src, dst, p_qe, p_ke, p_ve, p_buf1);

    // 6) classifier
    gemm_kernel<<<dim3(1, (NN + BM - 1) / BM), 256>>>(
        p_buf1, HIDD, nullptr, NN, clsW, HIDD, clsB, out, 64, 0);
}